// round 17
// baseline (speedup 1.0000x reference)
#include <cuda_runtime.h>
#include <cuda_bf16.h>

#define NTHREADS 1024
#define MAX_BLOCKS 2048

__device__ double g_dacc[2] = {0.0, 0.0};   // [0]=sum(bce*m), [1]=sum(m); last block resets
__device__ unsigned int g_ticket = 0;       // self-resetting via atomicInc wrap

// Fire-and-forget reduction with release semantics.
__device__ __forceinline__ void red_release_f64(double* p, double v) {
    asm volatile("red.release.gpu.global.add.f64 [%0], %1;" :: "l"(p), "d"(v) : "memory");
}

__device__ __forceinline__ double ldcg_f64(const double* p) {
    double v;
    asm volatile("ld.global.cg.f64 %0, [%1];" : "=d"(v) : "l"(p));
    return v;
}

__device__ __forceinline__ void accum_elem(float x, float p, float n, float y,
                                           float& s_bce, float& s_cnt) {
    float m   = (fminf(p, n) > 0.5f) ? 1.0f : 0.0f;
    float t   = __expf(-fabsf(x));                       // FMUL + MUFU.EX2
    float sp  = 0.69314718056f * __log2f(1.0f + t);      // FADD + MUFU.LG2 + FMUL
    float bce = fmaxf(x, 0.0f) - x * y + sp;
    s_bce += bce * m;
    s_cnt += m;
}

__device__ __forceinline__ void accum_vec(float4 xv, float4 pv, float4 nv, float y,
                                          float& s_bce, float& s_cnt) {
    accum_elem(xv.x, pv.x, nv.x, y, s_bce, s_cnt);
    accum_elem(xv.y, pv.y, nv.y, y, s_bce, s_cnt);
    accum_elem(xv.z, pv.z, nv.z, y, s_bce, s_cnt);
    accum_elem(xv.w, pv.w, nv.w, y, s_bce, s_cnt);
}

__global__ __launch_bounds__(NTHREADS, 2) void loss_kernel(
    const float4* __restrict__ x4,
    const float*  __restrict__ label,
    const float4* __restrict__ pm4,
    const float4* __restrict__ nm4,
    float* __restrict__ out,
    int hw4, int nblocks_total)
{
    const int   b    = blockIdx.y;
    const float y    = __ldg(&label[b]);
    const int   base = b * hw4;

    float s_bce = 0.0f;
    float s_cnt = 0.0f;

    // 1024 thr/block, 2 blocks/SM (launch_bounds pins regs to 32 so the full
    // RF fits). 288 blocks total: per-CTA overhead halves again vs R16.
    const int stride = gridDim.x * blockDim.x;
    for (int i = blockIdx.x * blockDim.x + threadIdx.x; i < hw4; i += stride) {
        float4 xv = __ldg(&x4 [base + i]);
        float4 pv = __ldg(&pm4[base + i]);
        float4 nv = __ldg(&nm4[base + i]);
        accum_vec(xv, pv, nv, y, s_bce, s_cnt);
    }

    // Warp reduction
    #pragma unroll
    for (int off = 16; off > 0; off >>= 1) {
        s_bce += __shfl_down_sync(0xFFFFFFFFu, s_bce, off);
        s_cnt += __shfl_down_sync(0xFFFFFFFFu, s_cnt, off);
    }

    // Block reduction (32 warps -> one warp of partials)
    __shared__ float sh_bce[32];
    __shared__ float sh_cnt[32];
    const int wid = threadIdx.x >> 5;
    const int lid = threadIdx.x & 31;
    if (lid == 0) { sh_bce[wid] = s_bce; sh_cnt[wid] = s_cnt; }
    __syncthreads();

    if (threadIdx.x < 32) {
        float bsum = sh_bce[lid];
        float csum = sh_cnt[lid];
        #pragma unroll
        for (int off = 16; off > 0; off >>= 1) {
            bsum += __shfl_down_sync(0xFFFFFFFFu, bsum, off);
            csum += __shfl_down_sync(0xFFFFFFFFu, csum, off);
        }
        if (lid == 0) {
            red_release_f64(&g_dacc[0], (double)bsum);
            red_release_f64(&g_dacc[1], (double)csum);
            unsigned t;
            asm volatile("atom.acquire.gpu.global.inc.u32 %0, [%1], %2;"
                         : "=r"(t) : "l"(&g_ticket), "r"((unsigned)nblocks_total - 1)
                         : "memory");
            if (t == (unsigned)nblocks_total - 1) {
                double b2 = ldcg_f64(&g_dacc[0]);
                double c2 = ldcg_f64(&g_dacc[1]);
                // Reset for the next graph replay (self-cleaning).
                g_dacc[0] = 0.0;
                g_dacc[1] = 0.0;
                if (c2 < 1.0) c2 = 1.0;
                out[0] = (float)(b2 / c2);
            }
        }
    }
}

extern "C" void kernel_launch(void* const* d_in, const int* in_sizes, int n_in,
                              void* d_out, int out_size) {
    const float* x  = (const float*)d_in[0];  // cancer_logits (B,1,H,W)
    const float* y  = (const float*)d_in[1];  // label (B,)
    const float* pm = (const float*)d_in[2];  // prostate_mask
    const float* nm = (const float*)d_in[3];  // needle_mask

    int n   = in_sizes[0];   // B*H*W
    int nb  = in_sizes[1];   // B
    int hw4 = (n / nb) / 4;  // float4s per image

    // 2 blocks/SM at 1024 threads -> capacity 296; single wave needs
    // bpb * nb <= 296. For nb=32: bpb=9 -> 288 blocks.
    int bpb = (2 * 148) / nb;
    if (bpb < 1) bpb = 1;
    while (bpb * nb > MAX_BLOCKS && bpb > 1) bpb--;
    int nblocks_total = bpb * nb;

    dim3 grid(bpb, nb, 1);
    loss_kernel<<<grid, NTHREADS>>>(
        (const float4*)x, y, (const float4*)pm, (const float4*)nm,
        (float*)d_out, hw4, nblocks_total);
}